// round 9
// baseline (speedup 1.0000x reference)
#include <cuda_runtime.h>

#define BATCH 64
#define TDIM  2048
#define QDIM  512
#define KDIM  512

// Scratch (no allocations allowed in kernel_launch)
__device__ float g_mids[BATCH * KDIM];
__device__ float g_sums[BATCH];

// ---------------------------------------------------------------------------
// Kernel 1 (v3): mids[b,k] = sum_q W[k,q] * query[b,q].
// grid = 512: kt = x & 31 (32 tiles of 16 k), bt = x >> 5 (16 tiles of 4 b).
// 256 threads = 8 warps; each warp owns TWO k rows over full q=512 for 4
// batches: q float4 loaded once per (j,b) and reused for both k's (2x FMA
// per LDS vs R8), W = 8 coalesced LDG.128/warp, one 5-level shfl tree over
// 8 interleaved accumulators (40 shfl). smem fill is 2 unrolled float4
// iterations per thread (vs 8 scalar in R8). Block 0 zeroes g_sums.
// ---------------------------------------------------------------------------
__global__ void __launch_bounds__(256)
mids_kernel(const float* __restrict__ query,
            const float* __restrict__ W)
{
    const int kt = blockIdx.x & 31;   // 0..31 (16 k each)
    const int bt = blockIdx.x >> 5;   // 0..15 (4 b each)

    if (blockIdx.x == 0 && threadIdx.x < BATCH) g_sums[threadIdx.x] = 0.0f;

    __shared__ float q_s[4][QDIM];
    {
        // 4*512 floats = 512 float4; 256 threads -> exactly 2 each
        const float4* qg = reinterpret_cast<const float4*>(
            query + (size_t)bt * 4 * QDIM);
        float4* qs4 = reinterpret_cast<float4*>(&q_s[0][0]);
        qs4[threadIdx.x]       = qg[threadIdx.x];
        qs4[threadIdx.x + 256] = qg[threadIdx.x + 256];
    }
    __syncthreads();

    const int warp = threadIdx.x >> 5;
    const int lane = threadIdx.x & 31;
    const int k0   = kt * 16 + warp * 2;
    const int k1   = k0 + 1;

    // Two W rows: 4 coalesced float4 per lane each
    const float4* w4a = reinterpret_cast<const float4*>(W + (size_t)k0 * QDIM);
    const float4* w4b = reinterpret_cast<const float4*>(W + (size_t)k1 * QDIM);
    float4 wa[4], wb[4];
#pragma unroll
    for (int j = 0; j < 4; j++) {
        wa[j] = w4a[lane + 32 * j];
        wb[j] = w4b[lane + 32 * j];
    }

    float a[2][4] = {};
#pragma unroll
    for (int j = 0; j < 4; j++) {
        const int idx = lane + 32 * j;
        const float4 w0 = wa[j];
        const float4 w1 = wb[j];
#pragma unroll
        for (int bb = 0; bb < 4; bb++) {
            const float4 v = reinterpret_cast<const float4*>(q_s[bb])[idx];
            a[0][bb] += w0.x * v.x + w0.y * v.y + w0.z * v.z + w0.w * v.w;
            a[1][bb] += w1.x * v.x + w1.y * v.y + w1.z * v.z + w1.w * v.w;
        }
    }
#pragma unroll
    for (int o = 16; o; o >>= 1) {
#pragma unroll
        for (int bb = 0; bb < 4; bb++) {
            a[0][bb] += __shfl_xor_sync(0xffffffffu, a[0][bb], o);
            a[1][bb] += __shfl_xor_sync(0xffffffffu, a[1][bb], o);
        }
    }
    if (lane == 0) {
#pragma unroll
        for (int bb = 0; bb < 4; bb++) {
            const int b = bt * 4 + bb;
            g_mids[(size_t)b * KDIM + k0] = a[0][bb];
            g_mids[(size_t)b * KDIM + k1] = a[1][bb];
        }
    }
}

// ---------------------------------------------------------------------------
// Kernel 2 (measured best): e[b,t] = exp(tanh(key.mids+bias)); accumulate
// per-batch sums. tanh in (-1,1) -> exp bounded -> no max pass.
// grid = 64*32 = 2048 blocks (64 rows each), 256 threads = 8 warps.
// Each warp: 8 rows in ONE burst of 32 independent streaming LDG.128
// (warp-coalesced, 4 lines per LDG), then one interleaved 8-way shfl-reduce.
// ---------------------------------------------------------------------------
__global__ void __launch_bounds__(256)
scores_kernel(const float* __restrict__ key,
              const float* __restrict__ bias,
              float* __restrict__ out)
{
    const int b     = blockIdx.x >> 5;   // 0..63
    const int chunk = blockIdx.x & 31;   // 0..31 (64 rows each)

    __shared__ float ms[KDIM];
    __shared__ float blockSum;
    if (threadIdx.x == 0) blockSum = 0.0f;

    if (threadIdx.x < KDIM / 4) {
        const int i = threadIdx.x;
        reinterpret_cast<float4*>(ms)[i] =
            reinterpret_cast<const float4*>(g_mids + (size_t)b * KDIM)[i];
    }
    __syncthreads();

    const int warp = threadIdx.x >> 5;
    const int lane = threadIdx.x & 31;

    float4 m[4];
#pragma unroll
    for (int j = 0; j < 4; j++)
        m[j] = reinterpret_cast<const float4*>(ms)[lane + 32 * j];

    const int ta = chunk * 64 + warp * 8;
    const float4* kb = reinterpret_cast<const float4*>(
        key + ((size_t)b * TDIM + ta) * KDIM);

    float a0 = 0.f, a1 = 0.f, a2 = 0.f, a3 = 0.f;
    float a4 = 0.f, a5 = 0.f, a6 = 0.f, a7 = 0.f;
#pragma unroll
    for (int j = 0; j < 4; j++) {
        const int idx = lane + 32 * j;
        const float4 mv = m[j];
        float4 v0 = __ldcs(kb + idx + 0 * 128);
        float4 v1 = __ldcs(kb + idx + 1 * 128);
        float4 v2 = __ldcs(kb + idx + 2 * 128);
        float4 v3 = __ldcs(kb + idx + 3 * 128);
        float4 v4 = __ldcs(kb + idx + 4 * 128);
        float4 v5 = __ldcs(kb + idx + 5 * 128);
        float4 v6 = __ldcs(kb + idx + 6 * 128);
        float4 v7 = __ldcs(kb + idx + 7 * 128);
        a0 += v0.x * mv.x + v0.y * mv.y + v0.z * mv.z + v0.w * mv.w;
        a1 += v1.x * mv.x + v1.y * mv.y + v1.z * mv.z + v1.w * mv.w;
        a2 += v2.x * mv.x + v2.y * mv.y + v2.z * mv.z + v2.w * mv.w;
        a3 += v3.x * mv.x + v3.y * mv.y + v3.z * mv.z + v3.w * mv.w;
        a4 += v4.x * mv.x + v4.y * mv.y + v4.z * mv.z + v4.w * mv.w;
        a5 += v5.x * mv.x + v5.y * mv.y + v5.z * mv.z + v5.w * mv.w;
        a6 += v6.x * mv.x + v6.y * mv.y + v6.z * mv.z + v6.w * mv.w;
        a7 += v7.x * mv.x + v7.y * mv.y + v7.z * mv.z + v7.w * mv.w;
    }
#pragma unroll
    for (int o = 16; o; o >>= 1) {
        a0 += __shfl_xor_sync(0xffffffffu, a0, o);
        a1 += __shfl_xor_sync(0xffffffffu, a1, o);
        a2 += __shfl_xor_sync(0xffffffffu, a2, o);
        a3 += __shfl_xor_sync(0xffffffffu, a3, o);
        a4 += __shfl_xor_sync(0xffffffffu, a4, o);
        a5 += __shfl_xor_sync(0xffffffffu, a5, o);
        a6 += __shfl_xor_sync(0xffffffffu, a6, o);
        a7 += __shfl_xor_sync(0xffffffffu, a7, o);
    }

    if (lane == 0) {
        const float bv = bias[0];
        float4 e0, e1;
        e0.x = __expf(tanhf(a0 + bv));
        e0.y = __expf(tanhf(a1 + bv));
        e0.z = __expf(tanhf(a2 + bv));
        e0.w = __expf(tanhf(a3 + bv));
        e1.x = __expf(tanhf(a4 + bv));
        e1.y = __expf(tanhf(a5 + bv));
        e1.z = __expf(tanhf(a6 + bv));
        e1.w = __expf(tanhf(a7 + bv));
        float4* op = reinterpret_cast<float4*>(out + (size_t)b * TDIM + ta);
        op[0] = e0;
        op[1] = e1;
        atomicAdd(&blockSum,
                  ((e0.x + e0.y) + (e0.z + e0.w)) +
                  ((e1.x + e1.y) + (e1.z + e1.w)));
    }
    __syncthreads();
    if (threadIdx.x == 0) atomicAdd(&g_sums[b], blockSum);
}

// ---------------------------------------------------------------------------
// Kernel 3: normalize in place. 32768 float4s, b = (float4 index) / 512.
// ---------------------------------------------------------------------------
__global__ void norm_kernel(float* __restrict__ out)
{
    const int i = blockIdx.x * blockDim.x + threadIdx.x; // 0..32767
    const int b = i >> 9;  // 512 float4 per batch row (T=2048)
    const float inv = 1.0f / g_sums[b];
    float4* o4 = reinterpret_cast<float4*>(out);
    float4 v = o4[i];
    v.x *= inv; v.y *= inv; v.z *= inv; v.w *= inv;
    o4[i] = v;
}

// ---------------------------------------------------------------------------
// Inputs (metadata order): query [64,512], key [64,2048,512], W [512,512],
// bias [1]. Output: [64,2048] float32.
// ---------------------------------------------------------------------------
extern "C" void kernel_launch(void* const* d_in, const int* in_sizes, int n_in,
                              void* d_out, int out_size)
{
    const float* query = (const float*)d_in[0];
    const float* key   = (const float*)d_in[1];
    const float* W     = (const float*)d_in[2];
    const float* bias  = (const float*)d_in[3];
    float* out = (float*)d_out;

    mids_kernel<<<512, 256>>>(query, W);
    scores_kernel<<<BATCH * 32, 256>>>(key, bias, out);
    norm_kernel<<<(BATCH * TDIM / 4) / 256, 256>>>(out);
}